// round 14
// baseline (speedup 1.0000x reference)
#include <cuda_runtime.h>
#include <cuda_bf16.h>
#include <cuda_fp16.h>
#include <cstdint>

// ---------------------------------------------------------------------------
// WindowAttention (Swin shifted-window attention).
//   B=32, DIM=256, H=W=64, WIN=8, SHIFT=4, HEADS=8, HEAD_DIM=32, N=64
// R14: GEMM = R11 (best known). Attention bias+mask precomputed per
//      (head, window-class) into 512KB L2-resident table -> replaces ~180
//      ALU/LDS ops per thread with 16 float2 loads.
// ---------------------------------------------------------------------------

#define NWIN_TOT   2048
#define M_TOT      131072
#define C_DIM      256
#define N3C        768
#define HEADS      8
#define HD         32
#define NTOK       64
#define SCALE      0.17677669529663687f

__device__ __half g_Ah[(size_t)M_TOT * C_DIM];
__device__ __half g_Bh[(size_t)N3C * C_DIM];
__device__ __half g_qkvh[(size_t)3 * NWIN_TOT * HEADS * NTOK * HD];
__device__ float  g_comb[(size_t)HEADS * 4 * NTOK * NTOK];   // 512 KB

#define QKV_STRIDE ((size_t)NWIN_TOT * HEADS * NTOK * HD)

// ------------------------------ helpers -----------------------------------
__device__ __forceinline__ uint32_t smem_u32(const void* p) {
    uint32_t a;
    asm("{ .reg .u64 t; cvta.to.shared.u64 t, %1; cvt.u32.u64 %0, t; }"
        : "=r"(a) : "l"(p));
    return a;
}

__device__ __forceinline__ void cp16(uint32_t saddr, const void* g) {
    asm volatile("cp.async.cg.shared.global [%0], [%1], 16;" :: "r"(saddr), "l"(g));
}
#define CP_COMMIT()  asm volatile("cp.async.commit_group;" ::: "memory")
#define CP_WAIT(N)   asm volatile("cp.async.wait_group %0;" :: "n"(N) : "memory")

#define MBARRIER_INIT(a, cnt) \
    asm volatile("mbarrier.init.shared.b64 [%0], %1;" :: "r"((uint32_t)(a)), "r"((uint32_t)(cnt)) : "memory")
#define MBARRIER_ARRIVE(a) \
    asm volatile("mbarrier.arrive.shared.b64 _, [%0];" :: "r"((uint32_t)(a)) : "memory")
#define CP_MBAR_ARRIVE(a) \
    asm volatile("cp.async.mbarrier.arrive.noinc.shared.b64 [%0];" :: "r"((uint32_t)(a)) : "memory")

#define MBARRIER_WAIT_PARITY(a, par) do { \
    uint32_t _m = (uint32_t)(a); uint32_t _p = (uint32_t)(par); uint32_t _d; \
    asm volatile("{\n\t.reg .pred p;\n\t" \
        "mbarrier.try_wait.parity.acquire.cta.shared::cta.b64 p, [%1], %2;\n\t" \
        "selp.b32 %0, 1, 0, p;\n\t}" : "=r"(_d) : "r"(_m), "r"(_p) : "memory"); \
    if (!_d) { \
        asm volatile("{\n\t.reg .pred P1;\n\t" \
            "WL_%=:\n\t" \
            "mbarrier.try_wait.parity.acquire.cta.shared::cta.b64 P1, [%0], %1, 0x989680;\n\t" \
            "@P1 bra.uni WD_%=;\n\t" \
            "bra.uni WL_%=;\n\t" \
            "WD_%=:\n\t}" :: "r"(_m), "r"(_p) : "memory"); \
    } \
} while (0)

#define LDSM_X4(r, addr) \
    asm volatile("ldmatrix.sync.aligned.m8n8.x4.shared.b16 {%0,%1,%2,%3}, [%4];" \
        : "=r"((r)[0]), "=r"((r)[1]), "=r"((r)[2]), "=r"((r)[3]) : "r"(addr))
#define LDSM_X4T(r, addr) \
    asm volatile("ldmatrix.sync.aligned.m8n8.x4.trans.shared.b16 {%0,%1,%2,%3}, [%4];" \
        : "=r"((r)[0]), "=r"((r)[1]), "=r"((r)[2]), "=r"((r)[3]) : "r"(addr))

#define MMA_F16(d, a, b) \
    asm volatile("mma.sync.aligned.m16n8k16.row.col.f32.f16.f16.f32 " \
        "{%0,%1,%2,%3}, {%4,%5,%6,%7}, {%8,%9}, {%0,%1,%2,%3};" \
        : "+f"((d)[0]), "+f"((d)[1]), "+f"((d)[2]), "+f"((d)[3]) \
        : "r"((a)[0]), "r"((a)[1]), "r"((a)[2]), "r"((a)[3]), \
          "r"((b)[0]), "r"((b)[1]))

__device__ __forceinline__ uint32_t pack2h(float x, float y)
{
    __half2 a = __floats2half2_rn(x, y);
    return *(uint32_t*)&a;
}
__device__ __forceinline__ uint2 pack4h(float v0, float v1, float v2, float v3)
{
    uint2 r;
    r.x = pack2h(v0, v1);
    r.y = pack2h(v2, v3);
    return r;
}

// ---------------------------------------------------------------------------
// K0: gather + roll + window partition + fp32->fp16
// ---------------------------------------------------------------------------
__global__ void __launch_bounds__(256)
gather_split_kernel(const float* __restrict__ x)
{
    __shared__ float sm[64 * 65];
    const int blk = blockIdx.x;
    const int b  = blk >> 6;
    const int wy = (blk >> 3) & 7;
    const int wx = blk & 7;
    const int tid = threadIdx.x;

    uint2* dh = (uint2*)g_Ah + (size_t)blk * 4096;
    const float* xb = x + ((size_t)b << 20);

#pragma unroll 1
    for (int cc = 0; cc < 4; ++cc) {
#pragma unroll
        for (int it = 0; it < 16; ++it) {
            int idx = it * 256 + tid;
            int cl = idx >> 6;
            int t  = idx & 63;
            int i = t >> 3, j = t & 7;
            int gh = (wy * 8 + i + 4) & 63;
            int gw = (wx * 8 + j + 4) & 63;
            sm[t * 65 + cl] = xb[((size_t)(cc * 64 + cl) << 12) + gh * 64 + gw];
        }
        __syncthreads();
#pragma unroll
        for (int it = 0; it < 4; ++it) {
            int idx = it * 256 + tid;
            int t  = idx >> 4;
            int cq = idx & 15;
            const float* s = sm + t * 65 + cq * 4;
            dh[t * 64 + cc * 16 + cq] = pack4h(s[0], s[1], s[2], s[3]);
        }
        __syncthreads();
    }
}

// ---------------------------------------------------------------------------
// K0b: transpose qkv_w [K=256][N=768] -> B [N][K] fp16
// ---------------------------------------------------------------------------
__global__ void __launch_bounds__(256)
transW_kernel(const float* __restrict__ W)
{
    int g = blockIdx.x * 256 + threadIdx.x;
    int n = g >> 6;
    int k4 = (g & 63) * 4;
    float v[4];
#pragma unroll
    for (int r = 0; r < 4; ++r) v[r] = W[(size_t)(k4 + r) * N3C + n];
    ((uint2*)g_Bh)[(size_t)n * 64 + (k4 >> 2)] = pack4h(v[0], v[1], v[2], v[3]);
}

// ---------------------------------------------------------------------------
// K0c: combined bias+mask tables: g_comb[head][cls][t][s], cls = wy7*2 + wx7
// ---------------------------------------------------------------------------
__global__ void __launch_bounds__(256)
combined_bias_kernel(const float* __restrict__ table)
{
    const int hc = blockIdx.x;           // 0..31 = head*4 + cls
    const int h = hc >> 2, cls = hc & 3;
    float* dst = g_comb + ((size_t)hc << 12);
#pragma unroll
    for (int it = 0; it < 16; ++it) {
        int idx = it * 256 + threadIdx.x;   // 0..4095
        int t = idx >> 6, s = idx & 63;
        int yi = t >> 3, xi = t & 7;
        int ys = s >> 3, xs = s & 7;
        int bidx = (yi - ys + 7) * 15 + (xi - xs + 7);
        int rt = ((cls & 2) ? ((yi < 4) ? 1 : 2) : 0) * 3
               + ((cls & 1) ? ((xi < 4) ? 1 : 2) : 0);
        int rs = ((cls & 2) ? ((ys < 4) ? 1 : 2) : 0) * 3
               + ((cls & 1) ? ((xs < 4) ? 1 : 2) : 0);
        dst[idx] = table[bidx * 8 + h] + ((rt != rs) ? -100.0f : 0.0f);
    }
}

// ---------------------------------------------------------------------------
// K1: fp16 HMMA QKV GEMM (R11): mbarrier ring, K-chunk 64, 3 stages, 2 CTA/SM
// ---------------------------------------------------------------------------
#define ROWB3 144
#define ARR3  (128 * ROWB3)
#define STG3  (2 * ARR3)
#define NSTG  3
#define NCHK  4

__global__ void __launch_bounds__(256, 2)
qkv_mma_kernel(const float* __restrict__ bias)
{
    extern __shared__ __align__(128) char dsm[];
    __shared__ __align__(16) unsigned long long s_mb[2 * NSTG];
    const uint32_t su = smem_u32(dsm);
    const uint32_t mb = smem_u32(&s_mb[0]);
#define MB_FULL(s)  (mb + (uint32_t)(s) * 16u)
#define MB_EMPTY(s) (mb + (uint32_t)(s) * 16u + 8u)

    const int tid  = threadIdx.x;
    const int lane = tid & 31;
    const int wid  = tid >> 5;
    const int wm   = wid >> 1;
    const int wn   = wid & 1;
    const int n0   = blockIdx.x * 128;
    const int m0   = blockIdx.y * 128;

    const __half* pA = g_Ah + (size_t)m0 * C_DIM;
    const __half* pB = g_Bh + (size_t)n0 * C_DIM;

    const int ldSeg = tid & 7;
    const int ldRow = tid >> 3;

    const uint32_t aRow = (uint32_t)(wm * 32 + (lane & 15)) * ROWB3
                        + (uint32_t)(lane >> 4) * 16;
    const uint32_t bRow = (uint32_t)(wn * 64 + ((lane >> 4) << 3) + (lane & 7)) * ROWB3
                        + (uint32_t)((lane >> 3) & 1) * 16;

    if (tid == 0) {
#pragma unroll
        for (int s = 0; s < NSTG; ++s) {
            MBARRIER_INIT(MB_FULL(s), 256);
            MBARRIER_INIT(MB_EMPTY(s), 256);
        }
    }
    __syncthreads();

    float acc[2][8][4];
#pragma unroll
    for (int i = 0; i < 2; ++i)
#pragma unroll
        for (int j = 0; j < 8; ++j)
#pragma unroll
            for (int q = 0; q < 4; ++q) acc[i][j][q] = 0.f;

    auto produce = [&](int c, int st, int ep) {
        MBARRIER_WAIT_PARITY(MB_EMPTY(st), ep);
        const uint32_t sb = su + (uint32_t)st * STG3;
        const int kb = c * 64 + ldSeg * 8;
#pragma unroll
        for (int p = 0; p < 4; ++p) {
            int row = p * 32 + ldRow;
            uint32_t so = (uint32_t)row * ROWB3 + (uint32_t)ldSeg * 16;
            size_t gi = (size_t)row * C_DIM + kb;
            cp16(sb + so,        pA + gi);
            cp16(sb + ARR3 + so, pB + gi);
        }
        CP_MBAR_ARRIVE(MB_FULL(st));
    };

    produce(0, 0, 1);
    produce(1, 1, 1);
    int pstage = 2, pphase = 1;
    int fstage = 0, fphase = 0;

#pragma unroll 1
    for (int c = 0; c < NCHK; ++c) {
        MBARRIER_WAIT_PARITY(MB_FULL(fstage), fphase);

        const uint32_t sb = su + (uint32_t)fstage * STG3;
        const uint32_t sA = sb;
        const uint32_t sB = sb + ARR3;

#pragma unroll
        for (int ks = 0; ks < 4; ++ks) {
            uint32_t ah[2][4];
#pragma unroll
            for (int mt = 0; mt < 2; ++mt) {
                uint32_t ao = aRow + (uint32_t)mt * (16 * ROWB3) + (uint32_t)ks * 32;
                LDSM_X4(ah[mt], sA + ao);
            }
#pragma unroll
            for (int np = 0; np < 4; ++np) {
                uint32_t bo = bRow + (uint32_t)np * (16 * ROWB3) + (uint32_t)ks * 32;
                uint32_t bh[4];
                LDSM_X4(bh, sB + bo);
#pragma unroll
                for (int half = 0; half < 2; ++half) {
                    int nt = np * 2 + half;
                    MMA_F16(acc[0][nt], ah[0], bh + half * 2);
                    MMA_F16(acc[1][nt], ah[1], bh + half * 2);
                }
            }
        }

        MBARRIER_ARRIVE(MB_EMPTY(fstage));
        if (c + 2 < NCHK) {
            produce(c + 2, pstage, pphase);
            if (++pstage == NSTG) { pstage = 0; pphase ^= 1; }
        }
        if (++fstage == NSTG) { fstage = 0; fphase ^= 1; }
    }

    // ---- epilogue: bias (+SCALE for Q), fp16 pack, scatter to g_qkvh ----
#pragma unroll
    for (int nt = 0; nt < 8; ++nt) {
        const int n = n0 + wn * 64 + nt * 8 + (lane & 3) * 2;
        const float2 bv = *(const float2*)(bias + n);
        const int which = n >> 8;
        const int head  = (n >> 5) & 7;
        const int d     = n & 31;
        const float scl = (which == 0) ? SCALE : 1.0f;
        const size_t nbase = (size_t)which * QKV_STRIDE + (size_t)head * (NTOK * HD) + d;
#pragma unroll
        for (int mt = 0; mt < 2; ++mt) {
            const int mb2 = m0 + wm * 32 + mt * 16 + (lane >> 2);
#pragma unroll
            for (int h = 0; h < 2; ++h) {
                const int m   = mb2 + h * 8;
                const int win = m >> 6;
                const int t   = m & 63;
                uint32_t pk = pack2h((acc[mt][nt][h * 2 + 0] + bv.x) * scl,
                                     (acc[mt][nt][h * 2 + 1] + bv.y) * scl);
                *(uint32_t*)(g_qkvh + nbase
                    + ((size_t)win * (HEADS * NTOK * HD) + (size_t)t * HD)) = pk;
            }
        }
    }
#undef MB_FULL
#undef MB_EMPTY
}

// ---------------------------------------------------------------------------
// K2: fp16 HMMA attention. grid = (2048, 8), 128 threads (4 warps).
// bias+mask via precomputed g_comb (L2-resident float2 loads).
// ---------------------------------------------------------------------------
#define ASTRIDE 80
#define AQ 0
#define AK 5120
#define AV 10240

__global__ void __launch_bounds__(128)
attn_kernel(float* __restrict__ out)
{
    __shared__ __align__(16) char smr[15360];

    const int win  = blockIdx.x;
    const int head = blockIdx.y;
    const int b  = win >> 6;
    const int wy = (win >> 3) & 7;
    const int wx = win & 7;

    const int tid  = threadIdx.x;
    const int lane = tid & 31;
    const int wid  = tid >> 5;
    const uint32_t sb = smem_u32(smr);

    const __half* qb = g_qkvh + (((size_t)win * HEADS + head) << 11);
    const __half* kb = qb + QKV_STRIDE;
    const __half* vb = qb + 2 * QKV_STRIDE;

#pragma unroll
    for (int it = 0; it < 2; ++it) {
        int idx = it * 128 + tid;
        int t = idx >> 2, seg = idx & 3;
        uint32_t dofs = (uint32_t)t * ASTRIDE + (uint32_t)seg * 16;
        size_t gofs = (size_t)t * 32 + seg * 8;
        cp16(sb + AQ + dofs, qb + gofs);
        cp16(sb + AK + dofs, kb + gofs);
        cp16(sb + AV + dofs, vb + gofs);
    }
    CP_COMMIT();

    const int cls = ((wy == 7) ? 2 : 0) | ((wx == 7) ? 1 : 0);
    const float* cb = g_comb + (((size_t)head * 4 + cls) << 12);

    CP_WAIT(0);
    __syncthreads();

    const int m0 = wid * 16;

    float accS[8][4];
#pragma unroll
    for (int i = 0; i < 8; ++i)
#pragma unroll
        for (int q = 0; q < 4; ++q) accS[i][q] = 0.f;

    const uint32_t aoff = (uint32_t)(m0 + (lane & 15)) * ASTRIDE + (uint32_t)(lane >> 4) * 16;
    const uint32_t koff = (uint32_t)(((lane >> 4) << 3) + (lane & 7)) * ASTRIDE
                        + (uint32_t)((lane >> 3) & 1) * 16;

#pragma unroll
    for (int kt = 0; kt < 2; ++kt) {
        uint32_t qf[4];
        LDSM_X4(qf, sb + AQ + aoff + kt * 32);
#pragma unroll
        for (int np = 0; np < 4; ++np) {
            uint32_t kf[4];
            LDSM_X4(kf, sb + AK + koff + (uint32_t)np * (16 * ASTRIDE) + kt * 32);
#pragma unroll
            for (int half = 0; half < 2; ++half)
                MMA_F16(accS[np * 2 + half], qf, kf + half * 2);
        }
    }

    const int r0 = m0 + (lane >> 2);
    const int r1 = r0 + 8;
    const int sbase = (lane & 3) * 2;

    // ---- bias + mask via combined table (float2 L2 loads) ----
#pragma unroll
    for (int nt = 0; nt < 8; ++nt) {
        int s0 = nt * 8 + sbase;
        float2 c0 = *(const float2*)(cb + r0 * 64 + s0);
        float2 c1 = *(const float2*)(cb + r1 * 64 + s0);
        accS[nt][0] += c0.x; accS[nt][1] += c0.y;
        accS[nt][2] += c1.x; accS[nt][3] += c1.y;
    }

    {
        float mx0 = -1e30f, mx1 = -1e30f;
#pragma unroll
        for (int nt = 0; nt < 8; ++nt) {
            mx0 = fmaxf(mx0, fmaxf(accS[nt][0], accS[nt][1]));
            mx1 = fmaxf(mx1, fmaxf(accS[nt][2], accS[nt][3]));
        }
#pragma unroll
        for (int o = 1; o < 4; o <<= 1) {
            mx0 = fmaxf(mx0, __shfl_xor_sync(0xFFFFFFFF, mx0, o));
            mx1 = fmaxf(mx1, __shfl_xor_sync(0xFFFFFFFF, mx1, o));
        }
        float sum0 = 0.f, sum1 = 0.f;
#pragma unroll
        for (int nt = 0; nt < 8; ++nt) {
            accS[nt][0] = __expf(accS[nt][0] - mx0);
            accS[nt][1] = __expf(accS[nt][1] - mx0);
            accS[nt][2] = __expf(accS[nt][2] - mx1);
            accS[nt][3] = __expf(accS[nt][3] - mx1);
            sum0 += accS[nt][0] + accS[nt][1];
            sum1 += accS[nt][2] + accS[nt][3];
        }
#pragma unroll
        for (int o = 1; o < 4; o <<= 1) {
            sum0 += __shfl_xor_sync(0xFFFFFFFF, sum0, o);
            sum1 += __shfl_xor_sync(0xFFFFFFFF, sum1, o);
        }
        float inv0 = 1.0f / sum0, inv1 = 1.0f / sum1;
#pragma unroll
        for (int nt = 0; nt < 8; ++nt) {
            accS[nt][0] *= inv0; accS[nt][1] *= inv0;
            accS[nt][2] *= inv1; accS[nt][3] *= inv1;
        }
    }

    uint32_t pf[4][4];
#pragma unroll
    for (int kt = 0; kt < 4; ++kt) {
        pf[kt][0] = pack2h(accS[2 * kt][0],     accS[2 * kt][1]);
        pf[kt][1] = pack2h(accS[2 * kt][2],     accS[2 * kt][3]);
        pf[kt][2] = pack2h(accS[2 * kt + 1][0], accS[2 * kt + 1][1]);
        pf[kt][3] = pack2h(accS[2 * kt + 1][2], accS[2 * kt + 1][3]);
    }

    float accO[4][4];
#pragma unroll
    for (int i = 0; i < 4; ++i)
#pragma unroll
        for (int q = 0; q < 4; ++q) accO[i][q] = 0.f;

    const uint32_t vrow = (uint32_t)((lane & 7) + ((lane >> 3) & 1) * 8) * ASTRIDE
                        + (uint32_t)((lane >> 4) << 3) * 2;
#pragma unroll
    for (int kt = 0; kt < 4; ++kt) {
#pragma unroll
        for (int np = 0; np < 2; ++np) {
            uint32_t vf[4];
            LDSM_X4T(vf, sb + AV + vrow + (uint32_t)kt * (16 * ASTRIDE) + (uint32_t)np * 32);
#pragma unroll
            for (int half = 0; half < 2; ++half)
                MMA_F16(accO[np * 2 + half], pf[kt], vf + half * 2);
        }
    }

    __syncthreads();
    float* Osm = (float*)smr;
#pragma unroll
    for (int nt = 0; nt < 4; ++nt) {
        int d0 = nt * 8 + sbase;
        Osm[r0 * 33 + d0]     = accO[nt][0];
        Osm[r0 * 33 + d0 + 1] = accO[nt][1];
        Osm[r1 * 33 + d0]     = accO[nt][2];
        Osm[r1 * 33 + d0 + 1] = accO[nt][3];
    }
    __syncthreads();

    size_t obase = ((size_t)b << 20) + ((size_t)head << 17);
#pragma unroll
    for (int it = 0; it < 16; ++it) {
        int idx = it * 128 + tid;
        int d = idx >> 6, t = idx & 63;
        int yi = t >> 3, xi = t & 7;
        int gh = (wy * 8 + yi + 4) & 63;
        int gw = (wx * 8 + xi + 4) & 63;
        out[obase + ((size_t)d << 12) + gh * 64 + gw] = Osm[t * 33 + d];
    }
}

// ---------------------------------------------------------------------------
extern "C" void kernel_launch(void* const* d_in, const int* in_sizes, int n_in,
                              void* d_out, int out_size)
{
    (void)in_sizes; (void)n_in; (void)out_size;
    const float* x    = (const float*)d_in[0];
    const float* qkvw = (const float*)d_in[1];
    const float* qkvb = (const float*)d_in[2];
    const float* tbl  = (const float*)d_in[3];
    float* out = (float*)d_out;

    cudaFuncSetAttribute(qkv_mma_kernel,
                         cudaFuncAttributeMaxDynamicSharedMemorySize, NSTG * STG3);

    gather_split_kernel<<<NWIN_TOT, 256>>>(x);
    transW_kernel<<<192, 256>>>(qkvw);
    combined_bias_kernel<<<32, 256>>>(tbl);
    qkv_mma_kernel<<<dim3(6, 1024), 256, NSTG * STG3>>>(qkvb);
    attn_kernel<<<dim3(NWIN_TOT, HEADS), 128>>>(out);
}

// round 15
// speedup vs baseline: 1.0338x; 1.0338x over previous
#include <cuda_runtime.h>
#include <cuda_bf16.h>
#include <cuda_fp16.h>
#include <cstdint>

// ---------------------------------------------------------------------------
// WindowAttention (Swin shifted-window attention).
//   B=32, DIM=256, H=W=64, WIN=8, SHIFT=4, HEADS=8, HEAD_DIM=32, N=64
// R15: GEMM chunk body software-pipelined — B fragment double-buffered,
//      A fragments prefetched one ks ahead (hides LDSM->MMA RAW latency
//      at 16 warps/SM). Rest identical to R11 (best: 327.6us).
// ---------------------------------------------------------------------------

#define NWIN_TOT   2048
#define M_TOT      131072
#define C_DIM      256
#define N3C        768
#define HEADS      8
#define HD         32
#define NTOK       64
#define SCALE      0.17677669529663687f

__device__ __half g_Ah[(size_t)M_TOT * C_DIM];
__device__ __half g_Bh[(size_t)N3C * C_DIM];
__device__ __half g_qkvh[(size_t)3 * NWIN_TOT * HEADS * NTOK * HD];

#define QKV_STRIDE ((size_t)NWIN_TOT * HEADS * NTOK * HD)

// ------------------------------ helpers -----------------------------------
__device__ __forceinline__ uint32_t smem_u32(const void* p) {
    uint32_t a;
    asm("{ .reg .u64 t; cvta.to.shared.u64 t, %1; cvt.u32.u64 %0, t; }"
        : "=r"(a) : "l"(p));
    return a;
}

__device__ __forceinline__ void cp16(uint32_t saddr, const void* g) {
    asm volatile("cp.async.cg.shared.global [%0], [%1], 16;" :: "r"(saddr), "l"(g));
}
#define CP_COMMIT()  asm volatile("cp.async.commit_group;" ::: "memory")
#define CP_WAIT(N)   asm volatile("cp.async.wait_group %0;" :: "n"(N) : "memory")

#define MBARRIER_INIT(a, cnt) \
    asm volatile("mbarrier.init.shared.b64 [%0], %1;" :: "r"((uint32_t)(a)), "r"((uint32_t)(cnt)) : "memory")
#define MBARRIER_ARRIVE(a) \
    asm volatile("mbarrier.arrive.shared.b64 _, [%0];" :: "r"((uint32_t)(a)) : "memory")
#define CP_MBAR_ARRIVE(a) \
    asm volatile("cp.async.mbarrier.arrive.noinc.shared.b64 [%0];" :: "r"((uint32_t)(a)) : "memory")

#define MBARRIER_WAIT_PARITY(a, par) do { \
    uint32_t _m = (uint32_t)(a); uint32_t _p = (uint32_t)(par); uint32_t _d; \
    asm volatile("{\n\t.reg .pred p;\n\t" \
        "mbarrier.try_wait.parity.acquire.cta.shared::cta.b64 p, [%1], %2;\n\t" \
        "selp.b32 %0, 1, 0, p;\n\t}" : "=r"(_d) : "r"(_m), "r"(_p) : "memory"); \
    if (!_d) { \
        asm volatile("{\n\t.reg .pred P1;\n\t" \
            "WL_%=:\n\t" \
            "mbarrier.try_wait.parity.acquire.cta.shared::cta.b64 P1, [%0], %1, 0x989680;\n\t" \
            "@P1 bra.uni WD_%=;\n\t" \
            "bra.uni WL_%=;\n\t" \
            "WD_%=:\n\t}" :: "r"(_m), "r"(_p) : "memory"); \
    } \
} while (0)

#define LDSM_X4(r, addr) \
    asm volatile("ldmatrix.sync.aligned.m8n8.x4.shared.b16 {%0,%1,%2,%3}, [%4];" \
        : "=r"((r)[0]), "=r"((r)[1]), "=r"((r)[2]), "=r"((r)[3]) : "r"(addr))
#define LDSM_X4T(r, addr) \
    asm volatile("ldmatrix.sync.aligned.m8n8.x4.trans.shared.b16 {%0,%1,%2,%3}, [%4];" \
        : "=r"((r)[0]), "=r"((r)[1]), "=r"((r)[2]), "=r"((r)[3]) : "r"(addr))

#define MMA_F16(d, a, b) \
    asm volatile("mma.sync.aligned.m16n8k16.row.col.f32.f16.f16.f32 " \
        "{%0,%1,%2,%3}, {%4,%5,%6,%7}, {%8,%9}, {%0,%1,%2,%3};" \
        : "+f"((d)[0]), "+f"((d)[1]), "+f"((d)[2]), "+f"((d)[3]) \
        : "r"((a)[0]), "r"((a)[1]), "r"((a)[2]), "r"((a)[3]), \
          "r"((b)[0]), "r"((b)[1]))

__device__ __forceinline__ uint32_t pack2h(float x, float y)
{
    __half2 a = __floats2half2_rn(x, y);
    return *(uint32_t*)&a;
}
__device__ __forceinline__ uint2 pack4h(float v0, float v1, float v2, float v3)
{
    uint2 r;
    r.x = pack2h(v0, v1);
    r.y = pack2h(v2, v3);
    return r;
}

// ---------------------------------------------------------------------------
// K0: gather + roll + window partition + fp32->fp16
// ---------------------------------------------------------------------------
__global__ void __launch_bounds__(256)
gather_split_kernel(const float* __restrict__ x)
{
    __shared__ float sm[64 * 65];
    const int blk = blockIdx.x;
    const int b  = blk >> 6;
    const int wy = (blk >> 3) & 7;
    const int wx = blk & 7;
    const int tid = threadIdx.x;

    uint2* dh = (uint2*)g_Ah + (size_t)blk * 4096;
    const float* xb = x + ((size_t)b << 20);

#pragma unroll 1
    for (int cc = 0; cc < 4; ++cc) {
#pragma unroll
        for (int it = 0; it < 16; ++it) {
            int idx = it * 256 + tid;
            int cl = idx >> 6;
            int t  = idx & 63;
            int i = t >> 3, j = t & 7;
            int gh = (wy * 8 + i + 4) & 63;
            int gw = (wx * 8 + j + 4) & 63;
            sm[t * 65 + cl] = xb[((size_t)(cc * 64 + cl) << 12) + gh * 64 + gw];
        }
        __syncthreads();
#pragma unroll
        for (int it = 0; it < 4; ++it) {
            int idx = it * 256 + tid;
            int t  = idx >> 4;
            int cq = idx & 15;
            const float* s = sm + t * 65 + cq * 4;
            dh[t * 64 + cc * 16 + cq] = pack4h(s[0], s[1], s[2], s[3]);
        }
        __syncthreads();
    }
}

// ---------------------------------------------------------------------------
// K0b: transpose qkv_w [K=256][N=768] -> B [N][K] fp16
// ---------------------------------------------------------------------------
__global__ void __launch_bounds__(256)
transW_kernel(const float* __restrict__ W)
{
    int g = blockIdx.x * 256 + threadIdx.x;
    int n = g >> 6;
    int k4 = (g & 63) * 4;
    float v[4];
#pragma unroll
    for (int r = 0; r < 4; ++r) v[r] = W[(size_t)(k4 + r) * N3C + n];
    ((uint2*)g_Bh)[(size_t)n * 64 + (k4 >> 2)] = pack4h(v[0], v[1], v[2], v[3]);
}

// ---------------------------------------------------------------------------
// K1: fp16 HMMA QKV GEMM, mbarrier ring, software-pipelined fragments.
// grid = (6, 1024), 256 threads (8 warps 4x2). Tile 128x128, K=256 in
// 4 chunks of 64, 3-stage ring, 2 CTAs/SM.
// ---------------------------------------------------------------------------
#define ROWB3 144
#define ARR3  (128 * ROWB3)
#define STG3  (2 * ARR3)
#define NSTG  3
#define NCHK  4

__global__ void __launch_bounds__(256, 2)
qkv_mma_kernel(const float* __restrict__ bias)
{
    extern __shared__ __align__(128) char dsm[];
    __shared__ __align__(16) unsigned long long s_mb[2 * NSTG];
    const uint32_t su = smem_u32(dsm);
    const uint32_t mb = smem_u32(&s_mb[0]);
#define MB_FULL(s)  (mb + (uint32_t)(s) * 16u)
#define MB_EMPTY(s) (mb + (uint32_t)(s) * 16u + 8u)

    const int tid  = threadIdx.x;
    const int lane = tid & 31;
    const int wid  = tid >> 5;
    const int wm   = wid >> 1;
    const int wn   = wid & 1;
    const int n0   = blockIdx.x * 128;
    const int m0   = blockIdx.y * 128;

    const __half* pA = g_Ah + (size_t)m0 * C_DIM;
    const __half* pB = g_Bh + (size_t)n0 * C_DIM;

    const int ldSeg = tid & 7;
    const int ldRow = tid >> 3;

    const uint32_t aRow = (uint32_t)(wm * 32 + (lane & 15)) * ROWB3
                        + (uint32_t)(lane >> 4) * 16;
    const uint32_t bRow = (uint32_t)(wn * 64 + ((lane >> 4) << 3) + (lane & 7)) * ROWB3
                        + (uint32_t)((lane >> 3) & 1) * 16;

    if (tid == 0) {
#pragma unroll
        for (int s = 0; s < NSTG; ++s) {
            MBARRIER_INIT(MB_FULL(s), 256);
            MBARRIER_INIT(MB_EMPTY(s), 256);
        }
    }
    __syncthreads();

    float acc[2][8][4];
#pragma unroll
    for (int i = 0; i < 2; ++i)
#pragma unroll
        for (int j = 0; j < 8; ++j)
#pragma unroll
            for (int q = 0; q < 4; ++q) acc[i][j][q] = 0.f;

    auto produce = [&](int c, int st, int ep) {
        MBARRIER_WAIT_PARITY(MB_EMPTY(st), ep);
        const uint32_t sb = su + (uint32_t)st * STG3;
        const int kb = c * 64 + ldSeg * 8;
#pragma unroll
        for (int p = 0; p < 4; ++p) {
            int row = p * 32 + ldRow;
            uint32_t so = (uint32_t)row * ROWB3 + (uint32_t)ldSeg * 16;
            size_t gi = (size_t)row * C_DIM + kb;
            cp16(sb + so,        pA + gi);
            cp16(sb + ARR3 + so, pB + gi);
        }
        CP_MBAR_ARRIVE(MB_FULL(st));
    };

    produce(0, 0, 1);
    produce(1, 1, 1);
    int pstage = 2, pphase = 1;
    int fstage = 0, fphase = 0;

#pragma unroll 1
    for (int c = 0; c < NCHK; ++c) {
        MBARRIER_WAIT_PARITY(MB_FULL(fstage), fphase);

        const uint32_t sb = su + (uint32_t)fstage * STG3;
        const uint32_t sA = sb;
        const uint32_t sB = sb + ARR3;

        // ---- software-pipelined fragment loop ----
        uint32_t ah[2][2][4];     // [buf][mt][regs]
        uint32_t bh[2][4];        // [buf][regs]

        LDSM_X4(ah[0][0], sA + aRow);
        LDSM_X4(ah[0][1], sA + aRow + 16 * ROWB3);
        LDSM_X4(bh[0],    sB + bRow);

#pragma unroll
        for (int ks = 0; ks < 4; ++ks) {
            const int cab = ks & 1;
            if (ks < 3) {
                uint32_t ao = aRow + (uint32_t)(ks + 1) * 32;
                LDSM_X4(ah[cab ^ 1][0], sA + ao);
                LDSM_X4(ah[cab ^ 1][1], sA + ao + 16 * ROWB3);
            }
#pragma unroll
            for (int np = 0; np < 4; ++np) {
                const int idx = ks * 4 + np;
                const int cbb = idx & 1;
                if (idx < 15) {
                    const int nidx = idx + 1;
                    const int nks = nidx >> 2, nnp = nidx & 3;
                    LDSM_X4(bh[cbb ^ 1],
                            sB + bRow + (uint32_t)nnp * (16 * ROWB3) + (uint32_t)nks * 32);
                }
                MMA_F16(acc[0][np * 2 + 0], ah[cab][0], bh[cbb] + 0);
                MMA_F16(acc[1][np * 2 + 0], ah[cab][1], bh[cbb] + 0);
                MMA_F16(acc[0][np * 2 + 1], ah[cab][0], bh[cbb] + 2);
                MMA_F16(acc[1][np * 2 + 1], ah[cab][1], bh[cbb] + 2);
            }
        }

        MBARRIER_ARRIVE(MB_EMPTY(fstage));
        if (c + 2 < NCHK) {
            produce(c + 2, pstage, pphase);
            if (++pstage == NSTG) { pstage = 0; pphase ^= 1; }
        }
        if (++fstage == NSTG) { fstage = 0; fphase ^= 1; }
    }

    // ---- epilogue: bias (+SCALE for Q), fp16 pack, scatter to g_qkvh ----
#pragma unroll
    for (int nt = 0; nt < 8; ++nt) {
        const int n = n0 + wn * 64 + nt * 8 + (lane & 3) * 2;
        const float2 bv = *(const float2*)(bias + n);
        const int which = n >> 8;
        const int head  = (n >> 5) & 7;
        const int d     = n & 31;
        const float scl = (which == 0) ? SCALE : 1.0f;
        const size_t nbase = (size_t)which * QKV_STRIDE + (size_t)head * (NTOK * HD) + d;
#pragma unroll
        for (int mt = 0; mt < 2; ++mt) {
            const int mb2 = m0 + wm * 32 + mt * 16 + (lane >> 2);
#pragma unroll
            for (int h = 0; h < 2; ++h) {
                const int m   = mb2 + h * 8;
                const int win = m >> 6;
                const int t   = m & 63;
                uint32_t pk = pack2h((acc[mt][nt][h * 2 + 0] + bv.x) * scl,
                                     (acc[mt][nt][h * 2 + 1] + bv.y) * scl);
                *(uint32_t*)(g_qkvh + nbase
                    + ((size_t)win * (HEADS * NTOK * HD) + (size_t)t * HD)) = pk;
            }
        }
    }
#undef MB_FULL
#undef MB_EMPTY
}

// ---------------------------------------------------------------------------
// K2: fp16 HMMA attention (R11 version). grid = (2048, 8), 128 threads.
// ---------------------------------------------------------------------------
#define ASTRIDE 80
#define AQ 0
#define AK 5120
#define AV 10240

__global__ void __launch_bounds__(128)
attn_kernel(const float* __restrict__ table,
            float* __restrict__ out)
{
    __shared__ __align__(16) char smr[15360];
    __shared__ float biasS[225];
    __shared__ int   regS[64];

    const int win  = blockIdx.x;
    const int head = blockIdx.y;
    const int b  = win >> 6;
    const int wy = (win >> 3) & 7;
    const int wx = win & 7;

    const int tid  = threadIdx.x;
    const int lane = tid & 31;
    const int wid  = tid >> 5;
    const uint32_t sb = smem_u32(smr);

    const __half* qb = g_qkvh + (((size_t)win * HEADS + head) << 11);
    const __half* kb = qb + QKV_STRIDE;
    const __half* vb = qb + 2 * QKV_STRIDE;

#pragma unroll
    for (int it = 0; it < 2; ++it) {
        int idx = it * 128 + tid;
        int t = idx >> 2, seg = idx & 3;
        uint32_t dofs = (uint32_t)t * ASTRIDE + (uint32_t)seg * 16;
        size_t gofs = (size_t)t * 32 + seg * 8;
        cp16(sb + AQ + dofs, qb + gofs);
        cp16(sb + AK + dofs, kb + gofs);
        cp16(sb + AV + dofs, vb + gofs);
    }
    CP_COMMIT();

    for (int i = tid; i < 225; i += 128) biasS[i] = table[i * 8 + head];
    if (tid < 64) {
        int yi = tid >> 3, xi = tid & 7;
        int h = wy * 8 + yi, w = wx * 8 + xi;
        int rh = (h < 56) ? 0 : ((h < 60) ? 1 : 2);
        int rw = (w < 56) ? 0 : ((w < 60) ? 1 : 2);
        regS[tid] = rh * 3 + rw;
    }
    CP_WAIT(0);
    __syncthreads();

    const int m0 = wid * 16;

    float accS[8][4];
#pragma unroll
    for (int i = 0; i < 8; ++i)
#pragma unroll
        for (int q = 0; q < 4; ++q) accS[i][q] = 0.f;

    const uint32_t aoff = (uint32_t)(m0 + (lane & 15)) * ASTRIDE + (uint32_t)(lane >> 4) * 16;
    const uint32_t koff = (uint32_t)(((lane >> 4) << 3) + (lane & 7)) * ASTRIDE
                        + (uint32_t)((lane >> 3) & 1) * 16;

#pragma unroll
    for (int kt = 0; kt < 2; ++kt) {
        uint32_t qf[4];
        LDSM_X4(qf, sb + AQ + aoff + kt * 32);
#pragma unroll
        for (int np = 0; np < 4; ++np) {
            uint32_t kf[4];
            LDSM_X4(kf, sb + AK + koff + (uint32_t)np * (16 * ASTRIDE) + kt * 32);
#pragma unroll
            for (int half = 0; half < 2; ++half)
                MMA_F16(accS[np * 2 + half], qf, kf + half * 2);
        }
    }

    const int r0 = m0 + (lane >> 2);
    const int r1 = r0 + 8;
    const int yi0 = r0 >> 3, xi0 = r0 & 7, rg0 = regS[r0];
    const int yi1 = r1 >> 3, xi1 = r1 & 7, rg1 = regS[r1];
#pragma unroll
    for (int nt = 0; nt < 8; ++nt) {
#pragma unroll
        for (int e = 0; e < 2; ++e) {
            int s  = nt * 8 + (lane & 3) * 2 + e;
            int ys = s >> 3, xs = s & 7;
            int rs = regS[s];
            accS[nt][e]     += biasS[(yi0 - ys + 7) * 15 + (xi0 - xs + 7)]
                             + (rs != rg0 ? -100.0f : 0.0f);
            accS[nt][2 + e] += biasS[(yi1 - ys + 7) * 15 + (xi1 - xs + 7)]
                             + (rs != rg1 ? -100.0f : 0.0f);
        }
    }

    {
        float mx0 = -1e30f, mx1 = -1e30f;
#pragma unroll
        for (int nt = 0; nt < 8; ++nt) {
            mx0 = fmaxf(mx0, fmaxf(accS[nt][0], accS[nt][1]));
            mx1 = fmaxf(mx1, fmaxf(accS[nt][2], accS[nt][3]));
        }
#pragma unroll
        for (int o = 1; o < 4; o <<= 1) {
            mx0 = fmaxf(mx0, __shfl_xor_sync(0xFFFFFFFF, mx0, o));
            mx1 = fmaxf(mx1, __shfl_xor_sync(0xFFFFFFFF, mx1, o));
        }
        float sum0 = 0.f, sum1 = 0.f;
#pragma unroll
        for (int nt = 0; nt < 8; ++nt) {
            accS[nt][0] = __expf(accS[nt][0] - mx0);
            accS[nt][1] = __expf(accS[nt][1] - mx0);
            accS[nt][2] = __expf(accS[nt][2] - mx1);
            accS[nt][3] = __expf(accS[nt][3] - mx1);
            sum0 += accS[nt][0] + accS[nt][1];
            sum1 += accS[nt][2] + accS[nt][3];
        }
#pragma unroll
        for (int o = 1; o < 4; o <<= 1) {
            sum0 += __shfl_xor_sync(0xFFFFFFFF, sum0, o);
            sum1 += __shfl_xor_sync(0xFFFFFFFF, sum1, o);
        }
        float inv0 = 1.0f / sum0, inv1 = 1.0f / sum1;
#pragma unroll
        for (int nt = 0; nt < 8; ++nt) {
            accS[nt][0] *= inv0; accS[nt][1] *= inv0;
            accS[nt][2] *= inv1; accS[nt][3] *= inv1;
        }
    }

    uint32_t pf[4][4];
#pragma unroll
    for (int kt = 0; kt < 4; ++kt) {
        pf[kt][0] = pack2h(accS[2 * kt][0],     accS[2 * kt][1]);
        pf[kt][1] = pack2h(accS[2 * kt][2],     accS[2 * kt][3]);
        pf[kt][2] = pack2h(accS[2 * kt + 1][0], accS[2 * kt + 1][1]);
        pf[kt][3] = pack2h(accS[2 * kt + 1][2], accS[2 * kt + 1][3]);
    }

    float accO[4][4];
#pragma unroll
    for (int i = 0; i < 4; ++i)
#pragma unroll
        for (int q = 0; q < 4; ++q) accO[i][q] = 0.f;

    const uint32_t vrow = (uint32_t)((lane & 7) + ((lane >> 3) & 1) * 8) * ASTRIDE
                        + (uint32_t)((lane >> 4) << 3) * 2;
#pragma unroll
    for (int kt = 0; kt < 4; ++kt) {
#pragma unroll
        for (int np = 0; np < 2; ++np) {
            uint32_t vf[4];
            LDSM_X4T(vf, sb + AV + vrow + (uint32_t)kt * (16 * ASTRIDE) + (uint32_t)np * 32);
#pragma unroll
            for (int half = 0; half < 2; ++half)
                MMA_F16(accO[np * 2 + half], pf[kt], vf + half * 2);
        }
    }

    __syncthreads();
    float* Osm = (float*)smr;
#pragma unroll
    for (int nt = 0; nt < 4; ++nt) {
        int d0 = nt * 8 + (lane & 3) * 2;
        Osm[r0 * 33 + d0]     = accO[nt][0];
        Osm[r0 * 33 + d0 + 1] = accO[nt][1];
        Osm[r1 * 33 + d0]     = accO[nt][2];
        Osm[r1 * 33 + d0 + 1] = accO[nt][3];
    }
    __syncthreads();

    size_t obase = ((size_t)b << 20) + ((size_t)head << 17);
#pragma unroll
    for (int it = 0; it < 16; ++it) {
        int idx = it * 128 + tid;
        int d = idx >> 6, t = idx & 63;
        int yi = t >> 3, xi = t & 7;
        int gh = (wy * 8 + yi + 4) & 63;
        int gw = (wx * 8 + xi + 4) & 63;
        out[obase + ((size_t)d << 12) + gh * 64 + gw] = Osm[t * 33 + d];
    }
}

// ---------------------------------------------------------------------------
extern "C" void kernel_launch(void* const* d_in, const int* in_sizes, int n_in,
                              void* d_out, int out_size)
{
    (void)in_sizes; (void)n_in; (void)out_size;
    const float* x    = (const float*)d_in[0];
    const float* qkvw = (const float*)d_in[1];
    const float* qkvb = (const float*)d_in[2];
    const float* tbl  = (const float*)d_in[3];
    float* out = (float*)d_out;

    cudaFuncSetAttribute(qkv_mma_kernel,
                         cudaFuncAttributeMaxDynamicSharedMemorySize, NSTG * STG3);

    gather_split_kernel<<<NWIN_TOT, 256>>>(x);
    transW_kernel<<<192, 256>>>(qkvw);
    qkv_mma_kernel<<<dim3(6, 1024), 256, NSTG * STG3>>>(qkvb);
    attn_kernel<<<dim3(NWIN_TOT, HEADS), 128>>>(tbl, out);
}

// round 16
// speedup vs baseline: 1.0524x; 1.0180x over previous
#include <cuda_runtime.h>
#include <cuda_bf16.h>
#include <cuda_fp16.h>
#include <cstdint>

// ---------------------------------------------------------------------------
// WindowAttention (Swin shifted-window attention).
//   B=32, DIM=256, H=W=64, WIN=8, SHIFT=4, HEADS=8, HEAD_DIM=32, N=64
// R16: attn reg-pressure cut: __launch_bounds__(128,9) (<=56 regs, 9 blk/SM)
//      + deferred softmax normalization (scale accO by 1/sum after PV).
//      GEMM/gather/transW identical to R15 (best: 323.6us).
// ---------------------------------------------------------------------------

#define NWIN_TOT   2048
#define M_TOT      131072
#define C_DIM      256
#define N3C        768
#define HEADS      8
#define HD         32
#define NTOK       64
#define SCALE      0.17677669529663687f

__device__ __half g_Ah[(size_t)M_TOT * C_DIM];
__device__ __half g_Bh[(size_t)N3C * C_DIM];
__device__ __half g_qkvh[(size_t)3 * NWIN_TOT * HEADS * NTOK * HD];

#define QKV_STRIDE ((size_t)NWIN_TOT * HEADS * NTOK * HD)

// ------------------------------ helpers -----------------------------------
__device__ __forceinline__ uint32_t smem_u32(const void* p) {
    uint32_t a;
    asm("{ .reg .u64 t; cvta.to.shared.u64 t, %1; cvt.u32.u64 %0, t; }"
        : "=r"(a) : "l"(p));
    return a;
}

__device__ __forceinline__ void cp16(uint32_t saddr, const void* g) {
    asm volatile("cp.async.cg.shared.global [%0], [%1], 16;" :: "r"(saddr), "l"(g));
}
#define CP_COMMIT()  asm volatile("cp.async.commit_group;" ::: "memory")
#define CP_WAIT(N)   asm volatile("cp.async.wait_group %0;" :: "n"(N) : "memory")

#define MBARRIER_INIT(a, cnt) \
    asm volatile("mbarrier.init.shared.b64 [%0], %1;" :: "r"((uint32_t)(a)), "r"((uint32_t)(cnt)) : "memory")
#define MBARRIER_ARRIVE(a) \
    asm volatile("mbarrier.arrive.shared.b64 _, [%0];" :: "r"((uint32_t)(a)) : "memory")
#define CP_MBAR_ARRIVE(a) \
    asm volatile("cp.async.mbarrier.arrive.noinc.shared.b64 [%0];" :: "r"((uint32_t)(a)) : "memory")

#define MBARRIER_WAIT_PARITY(a, par) do { \
    uint32_t _m = (uint32_t)(a); uint32_t _p = (uint32_t)(par); uint32_t _d; \
    asm volatile("{\n\t.reg .pred p;\n\t" \
        "mbarrier.try_wait.parity.acquire.cta.shared::cta.b64 p, [%1], %2;\n\t" \
        "selp.b32 %0, 1, 0, p;\n\t}" : "=r"(_d) : "r"(_m), "r"(_p) : "memory"); \
    if (!_d) { \
        asm volatile("{\n\t.reg .pred P1;\n\t" \
            "WL_%=:\n\t" \
            "mbarrier.try_wait.parity.acquire.cta.shared::cta.b64 P1, [%0], %1, 0x989680;\n\t" \
            "@P1 bra.uni WD_%=;\n\t" \
            "bra.uni WL_%=;\n\t" \
            "WD_%=:\n\t}" :: "r"(_m), "r"(_p) : "memory"); \
    } \
} while (0)

#define LDSM_X4(r, addr) \
    asm volatile("ldmatrix.sync.aligned.m8n8.x4.shared.b16 {%0,%1,%2,%3}, [%4];" \
        : "=r"((r)[0]), "=r"((r)[1]), "=r"((r)[2]), "=r"((r)[3]) : "r"(addr))
#define LDSM_X4T(r, addr) \
    asm volatile("ldmatrix.sync.aligned.m8n8.x4.trans.shared.b16 {%0,%1,%2,%3}, [%4];" \
        : "=r"((r)[0]), "=r"((r)[1]), "=r"((r)[2]), "=r"((r)[3]) : "r"(addr))

#define MMA_F16(d, a, b) \
    asm volatile("mma.sync.aligned.m16n8k16.row.col.f32.f16.f16.f32 " \
        "{%0,%1,%2,%3}, {%4,%5,%6,%7}, {%8,%9}, {%0,%1,%2,%3};" \
        : "+f"((d)[0]), "+f"((d)[1]), "+f"((d)[2]), "+f"((d)[3]) \
        : "r"((a)[0]), "r"((a)[1]), "r"((a)[2]), "r"((a)[3]), \
          "r"((b)[0]), "r"((b)[1]))

__device__ __forceinline__ uint32_t pack2h(float x, float y)
{
    __half2 a = __floats2half2_rn(x, y);
    return *(uint32_t*)&a;
}
__device__ __forceinline__ uint2 pack4h(float v0, float v1, float v2, float v3)
{
    uint2 r;
    r.x = pack2h(v0, v1);
    r.y = pack2h(v2, v3);
    return r;
}

// ---------------------------------------------------------------------------
// K0: gather + roll + window partition + fp32->fp16
// ---------------------------------------------------------------------------
__global__ void __launch_bounds__(256)
gather_split_kernel(const float* __restrict__ x)
{
    __shared__ float sm[64 * 65];
    const int blk = blockIdx.x;
    const int b  = blk >> 6;
    const int wy = (blk >> 3) & 7;
    const int wx = blk & 7;
    const int tid = threadIdx.x;

    uint2* dh = (uint2*)g_Ah + (size_t)blk * 4096;
    const float* xb = x + ((size_t)b << 20);

#pragma unroll 1
    for (int cc = 0; cc < 4; ++cc) {
#pragma unroll
        for (int it = 0; it < 16; ++it) {
            int idx = it * 256 + tid;
            int cl = idx >> 6;
            int t  = idx & 63;
            int i = t >> 3, j = t & 7;
            int gh = (wy * 8 + i + 4) & 63;
            int gw = (wx * 8 + j + 4) & 63;
            sm[t * 65 + cl] = xb[((size_t)(cc * 64 + cl) << 12) + gh * 64 + gw];
        }
        __syncthreads();
#pragma unroll
        for (int it = 0; it < 4; ++it) {
            int idx = it * 256 + tid;
            int t  = idx >> 4;
            int cq = idx & 15;
            const float* s = sm + t * 65 + cq * 4;
            dh[t * 64 + cc * 16 + cq] = pack4h(s[0], s[1], s[2], s[3]);
        }
        __syncthreads();
    }
}

// ---------------------------------------------------------------------------
// K0b: transpose qkv_w [K=256][N=768] -> B [N][K] fp16
// ---------------------------------------------------------------------------
__global__ void __launch_bounds__(256)
transW_kernel(const float* __restrict__ W)
{
    int g = blockIdx.x * 256 + threadIdx.x;
    int n = g >> 6;
    int k4 = (g & 63) * 4;
    float v[4];
#pragma unroll
    for (int r = 0; r < 4; ++r) v[r] = W[(size_t)(k4 + r) * N3C + n];
    ((uint2*)g_Bh)[(size_t)n * 64 + (k4 >> 2)] = pack4h(v[0], v[1], v[2], v[3]);
}

// ---------------------------------------------------------------------------
// K1: fp16 HMMA QKV GEMM, mbarrier ring, software-pipelined fragments (R15).
// ---------------------------------------------------------------------------
#define ROWB3 144
#define ARR3  (128 * ROWB3)
#define STG3  (2 * ARR3)
#define NSTG  3
#define NCHK  4

__global__ void __launch_bounds__(256, 2)
qkv_mma_kernel(const float* __restrict__ bias)
{
    extern __shared__ __align__(128) char dsm[];
    __shared__ __align__(16) unsigned long long s_mb[2 * NSTG];
    const uint32_t su = smem_u32(dsm);
    const uint32_t mb = smem_u32(&s_mb[0]);
#define MB_FULL(s)  (mb + (uint32_t)(s) * 16u)
#define MB_EMPTY(s) (mb + (uint32_t)(s) * 16u + 8u)

    const int tid  = threadIdx.x;
    const int lane = tid & 31;
    const int wid  = tid >> 5;
    const int wm   = wid >> 1;
    const int wn   = wid & 1;
    const int n0   = blockIdx.x * 128;
    const int m0   = blockIdx.y * 128;

    const __half* pA = g_Ah + (size_t)m0 * C_DIM;
    const __half* pB = g_Bh + (size_t)n0 * C_DIM;

    const int ldSeg = tid & 7;
    const int ldRow = tid >> 3;

    const uint32_t aRow = (uint32_t)(wm * 32 + (lane & 15)) * ROWB3
                        + (uint32_t)(lane >> 4) * 16;
    const uint32_t bRow = (uint32_t)(wn * 64 + ((lane >> 4) << 3) + (lane & 7)) * ROWB3
                        + (uint32_t)((lane >> 3) & 1) * 16;

    if (tid == 0) {
#pragma unroll
        for (int s = 0; s < NSTG; ++s) {
            MBARRIER_INIT(MB_FULL(s), 256);
            MBARRIER_INIT(MB_EMPTY(s), 256);
        }
    }
    __syncthreads();

    float acc[2][8][4];
#pragma unroll
    for (int i = 0; i < 2; ++i)
#pragma unroll
        for (int j = 0; j < 8; ++j)
#pragma unroll
            for (int q = 0; q < 4; ++q) acc[i][j][q] = 0.f;

    auto produce = [&](int c, int st, int ep) {
        MBARRIER_WAIT_PARITY(MB_EMPTY(st), ep);
        const uint32_t sb = su + (uint32_t)st * STG3;
        const int kb = c * 64 + ldSeg * 8;
#pragma unroll
        for (int p = 0; p < 4; ++p) {
            int row = p * 32 + ldRow;
            uint32_t so = (uint32_t)row * ROWB3 + (uint32_t)ldSeg * 16;
            size_t gi = (size_t)row * C_DIM + kb;
            cp16(sb + so,        pA + gi);
            cp16(sb + ARR3 + so, pB + gi);
        }
        CP_MBAR_ARRIVE(MB_FULL(st));
    };

    produce(0, 0, 1);
    produce(1, 1, 1);
    int pstage = 2, pphase = 1;
    int fstage = 0, fphase = 0;

#pragma unroll 1
    for (int c = 0; c < NCHK; ++c) {
        MBARRIER_WAIT_PARITY(MB_FULL(fstage), fphase);

        const uint32_t sb = su + (uint32_t)fstage * STG3;
        const uint32_t sA = sb;
        const uint32_t sB = sb + ARR3;

        uint32_t ah[2][2][4];
        uint32_t bh[2][4];

        LDSM_X4(ah[0][0], sA + aRow);
        LDSM_X4(ah[0][1], sA + aRow + 16 * ROWB3);
        LDSM_X4(bh[0],    sB + bRow);

#pragma unroll
        for (int ks = 0; ks < 4; ++ks) {
            const int cab = ks & 1;
            if (ks < 3) {
                uint32_t ao = aRow + (uint32_t)(ks + 1) * 32;
                LDSM_X4(ah[cab ^ 1][0], sA + ao);
                LDSM_X4(ah[cab ^ 1][1], sA + ao + 16 * ROWB3);
            }
#pragma unroll
            for (int np = 0; np < 4; ++np) {
                const int idx = ks * 4 + np;
                const int cbb = idx & 1;
                if (idx < 15) {
                    const int nidx = idx + 1;
                    const int nks = nidx >> 2, nnp = nidx & 3;
                    LDSM_X4(bh[cbb ^ 1],
                            sB + bRow + (uint32_t)nnp * (16 * ROWB3) + (uint32_t)nks * 32);
                }
                MMA_F16(acc[0][np * 2 + 0], ah[cab][0], bh[cbb] + 0);
                MMA_F16(acc[1][np * 2 + 0], ah[cab][1], bh[cbb] + 0);
                MMA_F16(acc[0][np * 2 + 1], ah[cab][0], bh[cbb] + 2);
                MMA_F16(acc[1][np * 2 + 1], ah[cab][1], bh[cbb] + 2);
            }
        }

        MBARRIER_ARRIVE(MB_EMPTY(fstage));
        if (c + 2 < NCHK) {
            produce(c + 2, pstage, pphase);
            if (++pstage == NSTG) { pstage = 0; pphase ^= 1; }
        }
        if (++fstage == NSTG) { fstage = 0; fphase ^= 1; }
    }

    // ---- epilogue: bias (+SCALE for Q), fp16 pack, scatter to g_qkvh ----
#pragma unroll
    for (int nt = 0; nt < 8; ++nt) {
        const int n = n0 + wn * 64 + nt * 8 + (lane & 3) * 2;
        const float2 bv = *(const float2*)(bias + n);
        const int which = n >> 8;
        const int head  = (n >> 5) & 7;
        const int d     = n & 31;
        const float scl = (which == 0) ? SCALE : 1.0f;
        const size_t nbase = (size_t)which * QKV_STRIDE + (size_t)head * (NTOK * HD) + d;
#pragma unroll
        for (int mt = 0; mt < 2; ++mt) {
            const int mb2 = m0 + wm * 32 + mt * 16 + (lane >> 2);
#pragma unroll
            for (int h = 0; h < 2; ++h) {
                const int m   = mb2 + h * 8;
                const int win = m >> 6;
                const int t   = m & 63;
                uint32_t pk = pack2h((acc[mt][nt][h * 2 + 0] + bv.x) * scl,
                                     (acc[mt][nt][h * 2 + 1] + bv.y) * scl);
                *(uint32_t*)(g_qkvh + nbase
                    + ((size_t)win * (HEADS * NTOK * HD) + (size_t)t * HD)) = pk;
            }
        }
    }
#undef MB_FULL
#undef MB_EMPTY
}

// ---------------------------------------------------------------------------
// K2: fp16 HMMA attention. grid = (2048, 8), 128 threads (4 warps).
// R16: <=56 regs (9 blocks/SM), deferred softmax normalization.
// ---------------------------------------------------------------------------
#define ASTRIDE 80
#define AQ 0
#define AK 5120
#define AV 10240

__global__ void __launch_bounds__(128, 9)
attn_kernel(const float* __restrict__ table,
            float* __restrict__ out)
{
    __shared__ __align__(16) char smr[15360];
    __shared__ float biasS[225];
    __shared__ int   regS[64];

    const int win  = blockIdx.x;
    const int head = blockIdx.y;
    const int b  = win >> 6;
    const int wy = (win >> 3) & 7;
    const int wx = win & 7;

    const int tid  = threadIdx.x;
    const int lane = tid & 31;
    const int wid  = tid >> 5;
    const uint32_t sb = smem_u32(smr);

    const __half* qb = g_qkvh + (((size_t)win * HEADS + head) << 11);
    const __half* kb = qb + QKV_STRIDE;
    const __half* vb = qb + 2 * QKV_STRIDE;

#pragma unroll
    for (int it = 0; it < 2; ++it) {
        int idx = it * 128 + tid;
        int t = idx >> 2, seg = idx & 3;
        uint32_t dofs = (uint32_t)t * ASTRIDE + (uint32_t)seg * 16;
        size_t gofs = (size_t)t * 32 + seg * 8;
        cp16(sb + AQ + dofs, qb + gofs);
        cp16(sb + AK + dofs, kb + gofs);
        cp16(sb + AV + dofs, vb + gofs);
    }
    CP_COMMIT();

    for (int i = tid; i < 225; i += 128) biasS[i] = table[i * 8 + head];
    if (tid < 64) {
        int yi = tid >> 3, xi = tid & 7;
        int h = wy * 8 + yi, w = wx * 8 + xi;
        int rh = (h < 56) ? 0 : ((h < 60) ? 1 : 2);
        int rw = (w < 56) ? 0 : ((w < 60) ? 1 : 2);
        regS[tid] = rh * 3 + rw;
    }
    CP_WAIT(0);
    __syncthreads();

    const int m0 = wid * 16;

    float accS[8][4];
#pragma unroll
    for (int i = 0; i < 8; ++i)
#pragma unroll
        for (int q = 0; q < 4; ++q) accS[i][q] = 0.f;

    const uint32_t aoff = (uint32_t)(m0 + (lane & 15)) * ASTRIDE + (uint32_t)(lane >> 4) * 16;
    const uint32_t koff = (uint32_t)(((lane >> 4) << 3) + (lane & 7)) * ASTRIDE
                        + (uint32_t)((lane >> 3) & 1) * 16;

#pragma unroll
    for (int kt = 0; kt < 2; ++kt) {
        uint32_t qf[4];
        LDSM_X4(qf, sb + AQ + aoff + kt * 32);
#pragma unroll
        for (int np = 0; np < 4; ++np) {
            uint32_t kf[4];
            LDSM_X4(kf, sb + AK + koff + (uint32_t)np * (16 * ASTRIDE) + kt * 32);
#pragma unroll
            for (int half = 0; half < 2; ++half)
                MMA_F16(accS[np * 2 + half], qf, kf + half * 2);
        }
    }

    const int r0 = m0 + (lane >> 2);
    const int r1 = r0 + 8;
    const int yi0 = r0 >> 3, xi0 = r0 & 7, rg0 = regS[r0];
    const int yi1 = r1 >> 3, xi1 = r1 & 7, rg1 = regS[r1];
#pragma unroll
    for (int nt = 0; nt < 8; ++nt) {
#pragma unroll
        for (int e = 0; e < 2; ++e) {
            int s  = nt * 8 + (lane & 3) * 2 + e;
            int ys = s >> 3, xs = s & 7;
            int rs = regS[s];
            accS[nt][e]     += biasS[(yi0 - ys + 7) * 15 + (xi0 - xs + 7)]
                             + (rs != rg0 ? -100.0f : 0.0f);
            accS[nt][2 + e] += biasS[(yi1 - ys + 7) * 15 + (xi1 - xs + 7)]
                             + (rs != rg1 ? -100.0f : 0.0f);
        }
    }

    // ---- softmax (unnormalized): max, exp, sum; keep inv for epilogue ----
    float inv0, inv1;
    {
        float mx0 = -1e30f, mx1 = -1e30f;
#pragma unroll
        for (int nt = 0; nt < 8; ++nt) {
            mx0 = fmaxf(mx0, fmaxf(accS[nt][0], accS[nt][1]));
            mx1 = fmaxf(mx1, fmaxf(accS[nt][2], accS[nt][3]));
        }
#pragma unroll
        for (int o = 1; o < 4; o <<= 1) {
            mx0 = fmaxf(mx0, __shfl_xor_sync(0xFFFFFFFF, mx0, o));
            mx1 = fmaxf(mx1, __shfl_xor_sync(0xFFFFFFFF, mx1, o));
        }
        float sum0 = 0.f, sum1 = 0.f;
#pragma unroll
        for (int nt = 0; nt < 8; ++nt) {
            accS[nt][0] = __expf(accS[nt][0] - mx0);
            accS[nt][1] = __expf(accS[nt][1] - mx0);
            accS[nt][2] = __expf(accS[nt][2] - mx1);
            accS[nt][3] = __expf(accS[nt][3] - mx1);
            sum0 += accS[nt][0] + accS[nt][1];
            sum1 += accS[nt][2] + accS[nt][3];
        }
#pragma unroll
        for (int o = 1; o < 4; o <<= 1) {
            sum0 += __shfl_xor_sync(0xFFFFFFFF, sum0, o);
            sum1 += __shfl_xor_sync(0xFFFFFFFF, sum1, o);
        }
        inv0 = 1.0f / sum0;
        inv1 = 1.0f / sum1;
    }

    // pack unnormalized P-hat to fp16 A-fragments
    uint32_t pf[4][4];
#pragma unroll
    for (int kt = 0; kt < 4; ++kt) {
        pf[kt][0] = pack2h(accS[2 * kt][0],     accS[2 * kt][1]);
        pf[kt][1] = pack2h(accS[2 * kt][2],     accS[2 * kt][3]);
        pf[kt][2] = pack2h(accS[2 * kt + 1][0], accS[2 * kt + 1][1]);
        pf[kt][3] = pack2h(accS[2 * kt + 1][2], accS[2 * kt + 1][3]);
    }

    float accO[4][4];
#pragma unroll
    for (int i = 0; i < 4; ++i)
#pragma unroll
        for (int q = 0; q < 4; ++q) accO[i][q] = 0.f;

    const uint32_t vrow = (uint32_t)((lane & 7) + ((lane >> 3) & 1) * 8) * ASTRIDE
                        + (uint32_t)((lane >> 4) << 3) * 2;
#pragma unroll
    for (int kt = 0; kt < 4; ++kt) {
#pragma unroll
        for (int np = 0; np < 2; ++np) {
            uint32_t vf[4];
            LDSM_X4T(vf, sb + AV + vrow + (uint32_t)kt * (16 * ASTRIDE) + (uint32_t)np * 32);
#pragma unroll
            for (int half = 0; half < 2; ++half)
                MMA_F16(accO[np * 2 + half], pf[kt], vf + half * 2);
        }
    }

    __syncthreads();
    float* Osm = (float*)smr;
#pragma unroll
    for (int nt = 0; nt < 4; ++nt) {
        int d0 = nt * 8 + (lane & 3) * 2;
        Osm[r0 * 33 + d0]     = accO[nt][0] * inv0;
        Osm[r0 * 33 + d0 + 1] = accO[nt][1] * inv0;
        Osm[r1 * 33 + d0]     = accO[nt][2] * inv1;
        Osm[r1 * 33 + d0 + 1] = accO[nt][3] * inv1;
    }
    __syncthreads();

    size_t obase = ((size_t)b << 20) + ((size_t)head << 17);
#pragma unroll
    for (int it = 0; it < 16; ++it) {
        int idx = it * 128 + tid;
        int d = idx >> 6, t = idx & 63;
        int yi = t >> 3, xi = t & 7;
        int gh = (wy * 8 + yi + 4) & 63;
        int gw = (wx * 8 + xi + 4) & 63;
        out[obase + ((size_t)d << 12) + gh * 64 + gw] = Osm[t * 33 + d];
    }
}

// ---------------------------------------------------------------------------
extern "C" void kernel_launch(void* const* d_in, const int* in_sizes, int n_in,
                              void* d_out, int out_size)
{
    (void)in_sizes; (void)n_in; (void)out_size;
    const float* x    = (const float*)d_in[0];
    const float* qkvw = (const float*)d_in[1];
    const float* qkvb = (const float*)d_in[2];
    const float* tbl  = (const float*)d_in[3];
    float* out = (float*)d_out;

    cudaFuncSetAttribute(qkv_mma_kernel,
                         cudaFuncAttributeMaxDynamicSharedMemorySize, NSTG * STG3);

    gather_split_kernel<<<NWIN_TOT, 256>>>(x);
    transW_kernel<<<192, 256>>>(qkvw);
    qkv_mma_kernel<<<dim3(6, 1024), 256, NSTG * STG3>>>(qkvb);
    attn_kernel<<<dim3(NWIN_TOT, HEADS), 128>>>(tbl, out);
}